// round 8
// baseline (speedup 1.0000x reference)
#include <cuda_runtime.h>
#include <math.h>

#define NB 16384
#define NM 50
#define ND 64
#define FULLM 0xffffffffu
#define NCHUNK (NB / 2)

__device__ unsigned g_next;
__global__ void reset_counter() { g_next = 0u; }

__global__ __launch_bounds__(32, 16)
void agree_kernel(
    const int* __restrict__ group_inputs,
    const int* __restrict__ item_inputs,
    const int* __restrict__ member_ids,
    const int* __restrict__ member_lengths,
    const float* __restrict__ user_table,
    const float* __restrict__ item_table,
    const float* __restrict__ group_table,
    const float* __restrict__ att_w1,
    const float* __restrict__ att_b1,
    const float* __restrict__ att_w2,
    const float* __restrict__ att_b2,
    const float* __restrict__ pred_w1,
    const float* __restrict__ pred_b1,
    const float* __restrict__ pred_w2,
    const float* __restrict__ pred_b2,
    float* __restrict__ out)
{
    // member pair staging, double buffered. One member = 72 words:
    // d[0..31] at 0..31, d[32..63] at 36..67 (pad kills bank aliasing).
    __shared__ __align__(16) float s_me[2][2][72];
    __shared__ __align__(16) float s_new[3 * ND];     // [elem | g | item_e]
    __shared__ __align__(16) float s_w1t[8 * 196];    // pred_w1 transposed, padded

    const int lane = threadIdx.x & 31;
    const int c0 = lane & 15;   // att hidden unit / float4-chunk this lane owns
    const int h  = lane >> 4;   // d-half AND "own member" of this lane

    // ======== CTA-lifetime constants (amortized over many rows) ========
    float wc[32], wb[32];       // W1a / W1b column c0, d-half h
    #pragma unroll
    for (int k = 0; k < 32; k++) wc[k] = att_w1[(h * 32 + k) * 16 + c0];
    #pragma unroll
    for (int k = 0; k < 32; k++) wb[k] = att_w1[(ND + h * 32 + k) * 16 + c0];
    const float b1c = att_b1[c0];
    const float w2c = att_w2[c0];
    const float b2  = att_b2[0];

    const int j = lane & 7;     // predict hidden unit
    const int q = lane >> 3;    // predict k-quarter
    const float pb1 = pred_b1[j];
    const float pw2 = pred_w2[j];
    const float pb2 = pred_b2[0];

    // transpose pred_w1 [192][8] -> s_w1t[j][192] (stride 196 vs bank aliasing)
    for (int idx = lane; idx < 192 * 8; idx += 32) {
        int kk = idx >> 3, jj = idx & 7;
        s_w1t[jj * 196 + kk] = pred_w1[idx];
    }
    __syncwarp();

    float* const s_item = &s_new[2 * ND];
    float* const meb = &s_me[0][0][0];               // buf stride 144 words
    const int stoff = 4 * c0 + ((c0 >= 8) ? 4 : 0);  // padded store offset

    // ======== chunked work-stealing over rows (2 rows per grab) ========
    int chunk = 0;
    if (lane == 0) chunk = (int)atomicAdd(&g_next, 1u);
    chunk = __shfl_sync(FULLM, chunk, 0);

    while (chunk < NCHUNK) {
        int nchunk = 0;
        if (lane == 0) nchunk = (int)atomicAdd(&g_next, 1u);  // prefetch grab

        #pragma unroll 1
        for (int rr = 0; rr < 2; rr++) {
            const int b = 2 * chunk + rr;

            // ---- row prologue ----
            const int len = member_lengths[b];    // member m valid iff m <= len
            const int npairs = (len >> 1) + 1;
            const int idsA = member_ids[b * NM + lane];
            const int idsB = (lane < NM - 32) ? member_ids[b * NM + 32 + lane] : 0;
            const float4 it4 =
                ((const float4*)(item_table + (size_t)item_inputs[b] * ND))[c0];
            ((float4*)s_item)[c0] = it4;   // both halves write identical data
            __syncwarp();

            // prefetch pair 0 (half h loads member h's row, float4 per lane)
            float4 r;
            {
                int mid = __shfl_sync(FULLM, idsA, h);
                r = ((const float4*)(user_table + (size_t)mid * ND))[c0];
            }

            // cconst[c0] = b1 + item_e @ W1b from persistent regs
            float cconst;
            {
                float cc = 0.f;
                const float4* si4 = (const float4*)(s_item + h * 32);
                #pragma unroll
                for (int i = 0; i < 8; i++) {
                    float4 v = si4[i];
                    cc = fmaf(v.x, wb[4 * i + 0], cc);
                    cc = fmaf(v.y, wb[4 * i + 1], cc);
                    cc = fmaf(v.z, wb[4 * i + 2], cc);
                    cc = fmaf(v.w, wb[4 * i + 3], cc);
                }
                cconst = cc + __shfl_xor_sync(FULLM, cc, 16) + b1c;
            }

            // plain-exp softmax (scores O(0.3) by construction — no max shift)
            float dsum = 0.f;
            float4 gq = make_float4(0.f, 0.f, 0.f, 0.f);

            #pragma unroll 1
            for (int p = 0; p < npairs; p++) {
                float* mb = meb + (p & 1) * 144;

                // stage pair p; keep own-member chunk in regs
                *(float4*)(mb + h * 72 + stoff) = r;
                float4 cur = r;
                __syncwarp();

                // prefetch pair p+1
                if (p + 1 < npairs) {
                    int m = 2 * (p + 1) + h;
                    int mid = __shfl_sync(FULLM, (m < 32) ? idsA : idsB, m & 31);
                    r = ((const float4*)(user_table + (size_t)mid * ND))[c0];
                }

                // partial dots over this lane's 32-d slice, both members
                const float4* me0 = (const float4*)(mb + h * 36);
                const float4* me1 = (const float4*)(mb + 72 + h * 36);
                float p0a = 0.f, p0b = 0.f, p1a = 0.f, p1b = 0.f;
                #pragma unroll
                for (int i = 0; i < 8; i += 2) {
                    float4 a = me0[i];
                    p0a = fmaf(a.x, wc[4 * i + 0], p0a);
                    p0a = fmaf(a.y, wc[4 * i + 1], p0a);
                    p0a = fmaf(a.z, wc[4 * i + 2], p0a);
                    p0a = fmaf(a.w, wc[4 * i + 3], p0a);
                    float4 a2 = me0[i + 1];
                    p0b = fmaf(a2.x, wc[4 * i + 4], p0b);
                    p0b = fmaf(a2.y, wc[4 * i + 5], p0b);
                    p0b = fmaf(a2.z, wc[4 * i + 6], p0b);
                    p0b = fmaf(a2.w, wc[4 * i + 7], p0b);
                    float4 e = me1[i];
                    p1a = fmaf(e.x, wc[4 * i + 0], p1a);
                    p1a = fmaf(e.y, wc[4 * i + 1], p1a);
                    p1a = fmaf(e.z, wc[4 * i + 2], p1a);
                    p1a = fmaf(e.w, wc[4 * i + 3], p1a);
                    float4 e2 = me1[i + 1];
                    p1b = fmaf(e2.x, wc[4 * i + 4], p1b);
                    p1b = fmaf(e2.y, wc[4 * i + 5], p1b);
                    p1b = fmaf(e2.z, wc[4 * i + 6], p1b);
                    p1b = fmaf(e2.w, wc[4 * i + 7], p1b);
                }
                float p0 = p0a + p0b;   // member0, this lane's d-half
                float p1 = p1a + p1b;   // member1, this lane's d-half

                // own-member assembly + disjoint butterfly (as R6)
                float u = h ? p1 : p0;
                float v = h ? p0 : p1;
                float A = u + __shfl_xor_sync(FULLM, v, 16);
                float t = fmaxf(A + cconst, 0.f) * w2c;
                t += __shfl_xor_sync(FULLM, t, 1);
                t += __shfl_xor_sync(FULLM, t, 2);
                t += __shfl_xor_sync(FULLM, t, 4);
                t += __shfl_xor_sync(FULLM, t, 8);

                // own-member weight; h=0 always valid in-loop
                float e = (2 * p + h <= len) ? __expf(t + b2) : 0.f;
                dsum += e;
                gq.x = fmaf(e, cur.x, gq.x);
                gq.y = fmaf(e, cur.y, gq.y);
                gq.z = fmaf(e, cur.z, gq.z);
                gq.w = fmaf(e, cur.w, gq.w);
            }

            // ---- cross-half combine: pooled g + group embedding ----
            gq.x += __shfl_xor_sync(FULLM, gq.x, 16);
            gq.y += __shfl_xor_sync(FULLM, gq.y, 16);
            gq.z += __shfl_xor_sync(FULLM, gq.z, 16);
            gq.w += __shfl_xor_sync(FULLM, gq.w, 16);
            dsum += __shfl_xor_sync(FULLM, dsum, 16);
            const float inv = 1.0f / dsum;

            const size_t gid = (size_t)group_inputs[b];
            float4 grp = ((const float4*)(group_table + gid * ND))[c0];

            float4 gg, el;
            gg.x = fmaf(gq.x, inv, grp.x);  el.x = gg.x * it4.x;
            gg.y = fmaf(gq.y, inv, grp.y);  el.y = gg.y * it4.y;
            gg.z = fmaf(gq.z, inv, grp.z);  el.z = gg.z * it4.z;
            gg.w = fmaf(gq.w, inv, grp.w);  el.w = gg.w * it4.w;

            ((float4*)&s_new[0])[c0]  = el;   // elem
            ((float4*)&s_new[ND])[c0] = gg;   // g  (item already at s_new[2*ND])
            __syncwarp();

            // ---- predict MLP: new_e[192] -> 8 -> 1 -> sigmoid (float4) ----
            float ph = 0.f;
            {
                const float4* sn4 = (const float4*)s_new;
                const float4* wt4 = (const float4*)(s_w1t + j * 196 + q * 48);
                #pragma unroll
                for (int i = 0; i < 12; i++) {
                    float4 a = sn4[q * 12 + i];
                    float4 wv = wt4[i];
                    ph = fmaf(a.x, wv.x, ph);
                    ph = fmaf(a.y, wv.y, ph);
                    ph = fmaf(a.z, wv.z, ph);
                    ph = fmaf(a.w, wv.w, ph);
                }
            }
            ph += __shfl_xor_sync(FULLM, ph, 8);
            ph += __shfl_xor_sync(FULLM, ph, 16);

            float t2 = fmaxf(ph + pb1, 0.f) * pw2;
            t2 += __shfl_xor_sync(FULLM, t2, 1);
            t2 += __shfl_xor_sync(FULLM, t2, 2);
            t2 += __shfl_xor_sync(FULLM, t2, 4);

            if (lane == 0) {
                float z = t2 + pb2;
                out[b] = 1.0f / (1.0f + __expf(-z));
            }
            __syncwarp();   // protect s_new/s_me reuse across rows
        }

        nchunk = __shfl_sync(FULLM, nchunk, 0);
        chunk = nchunk;
    }
}

extern "C" void kernel_launch(void* const* d_in, const int* in_sizes, int n_in,
                              void* d_out, int out_size) {
    (void)in_sizes; (void)n_in; (void)out_size;
    reset_counter<<<1, 1>>>();
    agree_kernel<<<148 * 16, 32>>>(
        (const int*)d_in[0],   // group_inputs
        (const int*)d_in[1],   // item_inputs
        (const int*)d_in[2],   // member_ids
        (const int*)d_in[3],   // member_lengths
        (const float*)d_in[4], // user_table
        (const float*)d_in[5], // item_table
        (const float*)d_in[6], // group_table
        (const float*)d_in[7], // att_w1
        (const float*)d_in[8], // att_b1
        (const float*)d_in[9], // att_w2
        (const float*)d_in[10],// att_b2
        (const float*)d_in[11],// pred_w1
        (const float*)d_in[12],// pred_b1
        (const float*)d_in[13],// pred_w2
        (const float*)d_in[14],// pred_b2
        (float*)d_out);
}